// round 2
// baseline (speedup 1.0000x reference)
#include <cuda_runtime.h>
#include <cuda_bf16.h>

// UpProjectFastHadamardTransform: out[r, :] = FWHT_8192( scatter(u[r, :], idx) ) / sqrt(8192)
//
// Factorization of the 8192-pt WHT (all H2 tensor-factor stages commute):
//   bits 12:9 -> register dim (phase 1, 4 stages)
//   bits  4:0 -> lane dim     (phase 2, 5 shfl_xor stages)
//   bits  8:5 -> warp dim     (phase 3: one smem transpose puts them in the
//                              register dim, then 4 register stages)
// One CTA per row: 512 threads x 16 f32 regs = 8192 values resident.

#define D_DIM 8192
#define K_DIM 1024
#define NTHREADS 512
#define NREGS 16

__global__ __launch_bounds__(NTHREADS)
void fwht_up_kernel(const float* __restrict__ u,
                    const int*   __restrict__ idx,
                    float*       __restrict__ out)
{
    __shared__ float z[D_DIM];

    const int t = threadIdx.x;       // 9 bits
    const int l = t & 31;            // lane  -> output bits 4:0
    const int w = t >> 5;            // warp  -> (phase 3) output bits 12:9
    const int row = blockIdx.x;

    // ---- zero + scatter into smem ----
    float4* z4 = reinterpret_cast<float4*>(z);
    #pragma unroll
    for (int q = 0; q < (D_DIM / 4) / NTHREADS; q++)
        z4[t + q * NTHREADS] = make_float4(0.f, 0.f, 0.f, 0.f);
    __syncthreads();

    const float* urow = u + (size_t)row * K_DIM;
    #pragma unroll
    for (int q = 0; q < K_DIM / NTHREADS; q++) {
        int k = t + q * NTHREADS;
        atomicAdd(&z[idx[k]], urow[k]);
    }
    __syncthreads();

    // ---- phase 1: load strided, 4 butterfly stages over register index (bits 12:9) ----
    float r[NREGS];
    #pragma unroll
    for (int j = 0; j < NREGS; j++)
        r[j] = z[j * NTHREADS + t];          // addr mod 32 == l : conflict-free

    #pragma unroll
    for (int s = 1; s < NREGS; s <<= 1) {
        #pragma unroll
        for (int m = 0; m < NREGS; m++) {
            if ((m & s) == 0) {
                float a = r[m], b = r[m + s];
                r[m]     = a + b;
                r[m + s] = a - b;
            }
        }
    }

    // ---- phase 2: 5 shuffle stages over lane bits (bits 4:0) ----
    #pragma unroll
    for (int s = 1; s < 32; s <<= 1) {
        #pragma unroll
        for (int j = 0; j < NREGS; j++) {
            float o = __shfl_xor_sync(0xffffffffu, r[j], s);
            r[j] = (l & s) ? (o - r[j]) : (r[j] + o);
        }
    }

    // ---- phase 3: smem transpose so warp bits 8:5 land in the register dim ----
    __syncthreads();   // all phase-1 reads of z must complete before overwrite
    #pragma unroll
    for (int j = 0; j < NREGS; j++)
        z[j * NTHREADS + t] = r[j];
    __syncthreads();

    float r2[NREGS];
    #pragma unroll
    for (int j2 = 0; j2 < NREGS; j2++)
        r2[j2] = z[w * NTHREADS + j2 * 32 + l];   // addr mod 32 == l : conflict-free

    #pragma unroll
    for (int s = 1; s < NREGS; s <<= 1) {
        #pragma unroll
        for (int m = 0; m < NREGS; m++) {
            if ((m & s) == 0) {
                float a = r2[m], b = r2[m + s];
                r2[m]     = a + b;
                r2[m + s] = a - b;
            }
        }
    }

    // ---- epilogue: scaled, coalesced stores (128B per (w,j2) per warp) ----
    const float scale = 0.0110485434560398047f;   // 1/sqrt(8192)
    float* orow = out + (size_t)row * D_DIM;
    #pragma unroll
    for (int j2 = 0; j2 < NREGS; j2++)
        orow[w * NTHREADS + j2 * 32 + l] = r2[j2] * scale;
}

extern "C" void kernel_launch(void* const* d_in, const int* in_sizes, int n_in,
                              void* d_out, int out_size)
{
    const float* u   = (const float*)d_in[0];
    const int*   idx = (const int*)d_in[1];
    float*       out = (float*)d_out;

    const int rows = in_sizes[0] / K_DIM;   // 4*2048 = 8192
    fwht_up_kernel<<<rows, NTHREADS>>>(u, idx, out);
}